// round 9
// baseline (speedup 1.0000x reference)
#include <cuda_runtime.h>
#include <cuda_bf16.h>
#include <cstdint>

#define DIN  256
#define DOUT 128
#define NP_MAX 100000
#define E_MAX  1600000
#define SLOPE 0.2f

// ---------------- scratch (static device globals; no allocation) ----------------
__device__ float g_Wh[2][(size_t)NP_MAX * DOUT];              // self tables fp32: 0=Wh_P, 1=Wh_A
__device__ __nv_bfloat16 g_Whm[4][(size_t)NP_MAX * DOUT];     // msg tables bf16: p2p,p2a,a2p,a2a
__device__ float g_ssrc[4][NP_MAX];   // type order: p2p, p2a, a2p, a2a
__device__ float g_sdst[4][NP_MAX];
__device__ int   g_cnt[4][NP_MAX];
__device__ int   g_cur[4][NP_MAX];
__device__ int   g_off[4][NP_MAX + 1];
__device__ int   g_part[4][512];
__device__ int   g_srcp[4][E_MAX];

struct BF4 { __nv_bfloat162 a, b; };   // 8 bytes = 4 bf16

// ================= TF32 tensor-core GEMM =================
#define ASTRIDE 36
#define BSTRIDE 136
#define ASZ (128 * ASTRIDE)
#define BSZ (32 * BSTRIDE)
#define SMEM_DYN ((2 * ASZ + 2 * BSZ) * 4)

struct GemmArgs {
    const float* A; int M;
    const float* W[3];
    const float* bias[3];
    float* C[3];                 // fp32 output (self) — used when Cb[g]==null
    __nv_bfloat16* Cb[3];        // bf16 output (messages) — used when non-null
    const float* av0[3]; float* s0[3];
    const float* av1[3]; float* s1[3];
};

__device__ __forceinline__ void cp_async16(void* smem_dst, const void* gsrc, bool pred) {
    uint32_t addr = (uint32_t)__cvta_generic_to_shared(smem_dst);
    int sz = pred ? 16 : 0;
    asm volatile("cp.async.cg.shared.global [%0], [%1], 16, %2;\n"
                 :: "r"(addr), "l"(gsrc), "r"(sz) : "memory");
}
__device__ __forceinline__ void cp_commit() {
    asm volatile("cp.async.commit_group;\n" ::: "memory");
}
__device__ __forceinline__ uint32_t f2tf32(float f) {
    uint32_t u;
    asm("cvt.rna.tf32.f32 %0, %1;" : "=r"(u) : "f"(f));
    return u;
}
__device__ __forceinline__ void mma_tf32(float c[4], const uint32_t a[4], uint32_t b0, uint32_t b1) {
    asm volatile(
        "mma.sync.aligned.m16n8k8.row.col.f32.tf32.tf32.f32 "
        "{%0,%1,%2,%3}, {%4,%5,%6,%7}, {%8,%9}, {%0,%1,%2,%3};"
        : "+f"(c[0]), "+f"(c[1]), "+f"(c[2]), "+f"(c[3])
        : "r"(a[0]), "r"(a[1]), "r"(a[2]), "r"(a[3]), "r"(b0), "r"(b1));
}

__global__ __launch_bounds__(256, 2) void gemm_tc_kernel(GemmArgs ga) {
    extern __shared__ float sm[];
    float* As = sm;
    float* Bs = sm + 2 * ASZ;

    const int g    = blockIdx.x;
    const int row0 = blockIdx.y * 128;
    const int tid  = threadIdx.x;
    const int lane = tid & 31;
    const int wid  = tid >> 5;
    const int wm   = wid & 1;
    const int wn   = wid >> 1;
    const int M    = ga.M;
    const float* A = ga.A;
    const float* W = ga.W[g];

    float c[4][4][4];
#pragma unroll
    for (int mf = 0; mf < 4; mf++)
#pragma unroll
        for (int nf = 0; nf < 4; nf++)
#pragma unroll
            for (int j = 0; j < 4; j++) c[mf][nf][j] = 0.f;

    auto loadA = [&](int k0, int buf) {
        float* dst = As + buf * ASZ;
#pragma unroll
        for (int i = 0; i < 4; i++) {
            int idx = tid + i * 256;
            int r = idx >> 3, c4 = idx & 7;
            int gr = row0 + r;
            int grc = gr < M ? gr : (M - 1);
            cp_async16(dst + r * ASTRIDE + c4 * 4,
                       A + (size_t)grc * DIN + k0 + c4 * 4, gr < M);
        }
    };
    auto loadB = [&](int k0, int buf) {
        float* dst = Bs + buf * BSZ;
#pragma unroll
        for (int i = 0; i < 4; i++) {
            int idx = tid + i * 256;
            int kr = idx >> 5, c4 = idx & 31;
            cp_async16(dst + kr * BSTRIDE + c4 * 4,
                       W + (size_t)(k0 + kr) * DOUT + c4 * 4, true);
        }
    };

    loadA(0, 0); loadB(0, 0); cp_commit();

    const int lq = lane >> 2;
    const int lr = lane & 3;

#pragma unroll 1
    for (int ch = 0; ch < 8; ch++) {
        if (ch < 7) {
            loadA((ch + 1) * 32, (ch + 1) & 1);
            loadB((ch + 1) * 32, (ch + 1) & 1);
            cp_commit();
            asm volatile("cp.async.wait_group 1;\n" ::: "memory");
        } else {
            asm volatile("cp.async.wait_group 0;\n" ::: "memory");
        }
        __syncthreads();

        const float* Ab = As + (ch & 1) * ASZ;
        const float* Bb = Bs + (ch & 1) * BSZ;

#pragma unroll
        for (int kk = 0; kk < 4; kk++) {
            uint32_t a[4][4];
#pragma unroll
            for (int mf = 0; mf < 4; mf++) {
                int r0 = wm * 64 + mf * 16 + lq;
                int k  = kk * 8 + lr;
                a[mf][0] = f2tf32(Ab[r0 * ASTRIDE + k]);
                a[mf][1] = f2tf32(Ab[(r0 + 8) * ASTRIDE + k]);
                a[mf][2] = f2tf32(Ab[r0 * ASTRIDE + k + 4]);
                a[mf][3] = f2tf32(Ab[(r0 + 8) * ASTRIDE + k + 4]);
            }
#pragma unroll
            for (int nf = 0; nf < 4; nf++) {
                int col = wn * 32 + nf * 8 + lq;
                int k   = kk * 8 + lr;
                uint32_t b0 = f2tf32(Bb[k * BSTRIDE + col]);
                uint32_t b1 = f2tf32(Bb[(k + 4) * BSTRIDE + col]);
#pragma unroll
                for (int mf = 0; mf < 4; mf++)
                    mma_tf32(c[mf][nf], a[mf], b0, b1);
            }
        }
        __syncthreads();
    }

    float* sdot = sm;
    sdot[tid] = 0.f;
    __syncthreads();

    const float* bias = ga.bias[g];
    float* C = ga.C[g];
    __nv_bfloat16* Cb = ga.Cb[g];
    const float* avA = ga.av0[g]; float* sA = ga.s0[g];
    const float* avB = ga.av1[g]; float* sB = ga.s1[g];

    float2 bv[4], aAv[4], aBv[4];
#pragma unroll
    for (int nf = 0; nf < 4; nf++) {
        int col = wn * 32 + nf * 8 + 2 * lr;
        bv[nf] = *(const float2*)(bias + col);
        aAv[nf] = make_float2(0.f, 0.f);
        aBv[nf] = make_float2(0.f, 0.f);
        if (avA) aAv[nf] = *(const float2*)(avA + col);
        if (avB) aBv[nf] = *(const float2*)(avB + col);
    }

#pragma unroll
    for (int mf = 0; mf < 4; mf++) {
        int rl_lo = wm * 64 + mf * 16 + lq;
        int rl_hi = rl_lo + 8;
        int rlo = row0 + rl_lo, rhi = row0 + rl_hi;
        float pAlo = 0.f, pAhi = 0.f, pBlo = 0.f, pBhi = 0.f;
#pragma unroll
        for (int nf = 0; nf < 4; nf++) {
            int col = wn * 32 + nf * 8 + 2 * lr;
            float v0 = c[mf][nf][0] + bv[nf].x;
            float v1 = c[mf][nf][1] + bv[nf].y;
            float v2 = c[mf][nf][2] + bv[nf].x;
            float v3 = c[mf][nf][3] + bv[nf].y;
            if (Cb) {
                if (rlo < M) *(__nv_bfloat162*)(Cb + (size_t)rlo * DOUT + col) =
                    __floats2bfloat162_rn(v0, v1);
                if (rhi < M) *(__nv_bfloat162*)(Cb + (size_t)rhi * DOUT + col) =
                    __floats2bfloat162_rn(v2, v3);
            } else {
                if (rlo < M) *(float2*)(C + (size_t)rlo * DOUT + col) = make_float2(v0, v1);
                if (rhi < M) *(float2*)(C + (size_t)rhi * DOUT + col) = make_float2(v2, v3);
            }
            pAlo += v0 * aAv[nf].x + v1 * aAv[nf].y;
            pAhi += v2 * aAv[nf].x + v3 * aAv[nf].y;
            pBlo += v0 * aBv[nf].x + v1 * aBv[nf].y;
            pBhi += v2 * aBv[nf].x + v3 * aBv[nf].y;
        }
#pragma unroll
        for (int off = 1; off <= 2; off <<= 1) {
            pAlo += __shfl_xor_sync(0xffffffffu, pAlo, off);
            pAhi += __shfl_xor_sync(0xffffffffu, pAhi, off);
            pBlo += __shfl_xor_sync(0xffffffffu, pBlo, off);
            pBhi += __shfl_xor_sync(0xffffffffu, pBhi, off);
        }
        if (lr == 0) {
            if (avA) { atomicAdd(&sdot[rl_lo], pAlo); atomicAdd(&sdot[rl_hi], pAhi); }
            if (avB) { atomicAdd(&sdot[128 + rl_lo], pBlo); atomicAdd(&sdot[128 + rl_hi], pBhi); }
        }
    }
    __syncthreads();
    if (tid < 128) {
        int row = row0 + tid;
        if (row < M) {
            if (sA) sA[row] = sdot[tid];
            if (sB) sB[row] = sdot[128 + tid];
        }
    }
}

// ================= batched CSR build (counting sort by dst, all 4 types) =================
struct Edges4 {
    const int* src[4];
    const int* dst[4];
    int E[4];
    int n[4];
};

__global__ __launch_bounds__(256) void hist_all_kernel(Edges4 es, int* __restrict__ cnt)
{
    int t = blockIdx.y;
    int i = blockIdx.x * blockDim.x + threadIdx.x;
    if (i < es.E[t]) atomicAdd(&cnt[t * NP_MAX + es.dst[t][i]], 1);
}

__global__ __launch_bounds__(256) void scan1_all_kernel(
    Edges4 es, const int* __restrict__ cnt, int* __restrict__ part)
{
    __shared__ int s[256];
    int t = blockIdx.y;
    int n = es.n[t];
    int tt = threadIdx.x;
    int i = blockIdx.x * 256 + tt;
    s[tt] = (i < n) ? cnt[t * NP_MAX + i] : 0;
    __syncthreads();
#pragma unroll
    for (int o = 128; o; o >>= 1) {
        if (tt < o) s[tt] += s[tt + o];
        __syncthreads();
    }
    if (tt == 0) part[t * 512 + blockIdx.x] = s[0];
}

__global__ __launch_bounds__(512) void scan2_all_kernel(Edges4 es, int* part)
{
    __shared__ int s[512];
    int ty = blockIdx.x;   // type
    int nb = (es.n[ty] + 255) / 256;
    int t = threadIdx.x;
    int v = (t < nb) ? part[ty * 512 + t] : 0;
    s[t] = v;
    __syncthreads();
#pragma unroll
    for (int o = 1; o < 512; o <<= 1) {
        int add = (t >= o) ? s[t - o] : 0;
        __syncthreads();
        s[t] += add;
        __syncthreads();
    }
    if (t < nb) part[ty * 512 + t] = t ? s[t - 1] : 0;  // exclusive
}

__global__ __launch_bounds__(256) void scan3_all_kernel(
    Edges4 es, const int* __restrict__ cnt, const int* __restrict__ part,
    int* __restrict__ off, int* __restrict__ cur)
{
    __shared__ int s[256];
    int ty = blockIdx.y;
    int n = es.n[ty], E = es.E[ty];
    int t = threadIdx.x;
    int i = blockIdx.x * 256 + t;
    int v = (i < n) ? cnt[ty * NP_MAX + i] : 0;
    s[t] = v;
    __syncthreads();
#pragma unroll
    for (int o = 1; o < 256; o <<= 1) {
        int add = (t >= o) ? s[t - o] : 0;
        __syncthreads();
        s[t] += add;
        __syncthreads();
    }
    int excl = (t ? s[t - 1] : 0) + part[ty * 512 + blockIdx.x];
    if (i < n) {
        off[ty * (NP_MAX + 1) + i] = excl;
        cur[ty * NP_MAX + i] = excl;
    }
    if (i == 0) off[ty * (NP_MAX + 1) + n] = E;
}

__global__ __launch_bounds__(256) void fill_all_kernel(
    Edges4 es, int* __restrict__ cur, int* __restrict__ srcp)
{
    int t = blockIdx.y;
    int i = blockIdx.x * blockDim.x + threadIdx.x;
    if (i >= es.E[t]) return;
    int pos = atomicAdd(&cur[t * NP_MAX + es.dst[t][i]], 1);
    srcp[(size_t)t * E_MAX + pos] = es.src[t][i];
}

// ================= fused GAT aggregate (bf16 messages) =================
__device__ __forceinline__ void gat_accum(
    const int* __restrict__ off, const int* __restrict__ srcp,
    const float* __restrict__ ssrc, float sd,
    const __nv_bfloat16* __restrict__ Whm, int d, int lane, float4& acc)
{
    int beg = off[d], end = off[d + 1];
    if (beg == end) return;

    // pass 1: denom (lane-strided, warp reduce)
    float den = 0.f;
    for (int i = beg + lane; i < end; i += 32) {
        float e = ssrc[srcp[i]] + sd;
        e = e > 0.f ? e : SLOPE * e;
        den += __expf(e);
    }
#pragma unroll
    for (int o = 16; o; o >>= 1) den += __shfl_xor_sync(0xffffffffu, den, o);
    float inv = 1.0f / den;

    // pass 2: weighted gather-accumulate, 2-edge unrolled
    int i = beg;
    for (; i + 1 < end; i += 2) {
        int s0 = srcp[i], s1 = srcp[i + 1];
        float e0 = ssrc[s0] + sd; e0 = e0 > 0.f ? e0 : SLOPE * e0;
        float e1 = ssrc[s1] + sd; e1 = e1 > 0.f ? e1 : SLOPE * e1;
        float w0 = __expf(e0) * inv;
        float w1 = __expf(e1) * inv;
        BF4 q0 = *(const BF4*)(Whm + (size_t)s0 * DOUT + lane * 4);
        BF4 q1 = *(const BF4*)(Whm + (size_t)s1 * DOUT + lane * 4);
        float2 q0a = __bfloat1622float2(q0.a), q0b = __bfloat1622float2(q0.b);
        float2 q1a = __bfloat1622float2(q1.a), q1b = __bfloat1622float2(q1.b);
        acc.x += w0 * q0a.x + w1 * q1a.x;
        acc.y += w0 * q0a.y + w1 * q1a.y;
        acc.z += w0 * q0b.x + w1 * q1b.x;
        acc.w += w0 * q0b.y + w1 * q1b.y;
    }
    if (i < end) {
        int s0 = srcp[i];
        float e0 = ssrc[s0] + sd; e0 = e0 > 0.f ? e0 : SLOPE * e0;
        float w0 = __expf(e0) * inv;
        BF4 q0 = *(const BF4*)(Whm + (size_t)s0 * DOUT + lane * 4);
        float2 q0a = __bfloat1622float2(q0.a), q0b = __bfloat1622float2(q0.b);
        acc.x += w0 * q0a.x; acc.y += w0 * q0a.y;
        acc.z += w0 * q0b.x; acc.w += w0 * q0b.y;
    }
}

__global__ __launch_bounds__(256) void gat_aggregate_kernel(
    const int* __restrict__ off1, const int* __restrict__ srcp1,
    const float* __restrict__ ssrc1, const float* __restrict__ sdst1,
    const __nv_bfloat16* __restrict__ Whm1,
    const int* __restrict__ off2, const int* __restrict__ srcp2,
    const float* __restrict__ ssrc2, const float* __restrict__ sdst2,
    const __nv_bfloat16* __restrict__ Whm2,
    const float* __restrict__ Whself, float* __restrict__ out, int n)
{
    int d    = (blockIdx.x * blockDim.x + threadIdx.x) >> 5;
    int lane = threadIdx.x & 31;
    if (d >= n) return;

    float4 acc = make_float4(0.f, 0.f, 0.f, 0.f);
    gat_accum(off1, srcp1, ssrc1, sdst1[d], Whm1, d, lane, acc);
    gat_accum(off2, srcp2, ssrc2, sdst2[d], Whm2, d, lane, acc);

    float4 self = *(const float4*)(Whself + (size_t)d * DOUT + lane * 4);
    float4 r;
    r.x = fmaxf(self.x + acc.x, 0.f);
    r.y = fmaxf(self.y + acc.y, 0.f);
    r.z = fmaxf(self.z + acc.z, 0.f);
    r.w = fmaxf(self.w + acc.w, 0.f);
    *(float4*)(out + (size_t)d * DOUT + lane * 4) = r;
}

// ---------------- host launcher ----------------
extern "C" void kernel_launch(void* const* d_in, const int* in_sizes, int n_in,
                              void* d_out, int out_size)
{
    (void)n_in; (void)out_size;
    const float* feat_P = (const float*)d_in[0];
    const float* feat_A = (const float*)d_in[1];

    Edges4 es;
    es.src[0] = (const int*)d_in[2]; es.dst[0] = (const int*)d_in[3];  // p2p
    es.src[1] = (const int*)d_in[4]; es.dst[1] = (const int*)d_in[5];  // p2a
    es.src[2] = (const int*)d_in[6]; es.dst[2] = (const int*)d_in[7];  // a2p
    es.src[3] = (const int*)d_in[8]; es.dst[3] = (const int*)d_in[9];  // a2a
    es.E[0] = in_sizes[2]; es.E[1] = in_sizes[4];
    es.E[2] = in_sizes[6]; es.E[3] = in_sizes[8];

    const float* W_P   = (const float*)d_in[10]; const float* b_P   = (const float*)d_in[11];
    const float* W_A   = (const float*)d_in[12]; const float* b_A   = (const float*)d_in[13];
    const float* W_p2p = (const float*)d_in[14]; const float* b_p2p = (const float*)d_in[15];
    const float* W_p2a = (const float*)d_in[16]; const float* b_p2a = (const float*)d_in[17];
    const float* W_a2p = (const float*)d_in[18]; const float* b_a2p = (const float*)d_in[19];
    const float* W_a2a = (const float*)d_in[20]; const float* b_a2a = (const float*)d_in[21];
    const float* a_p2p = (const float*)d_in[22];
    const float* a_p2a = (const float*)d_in[23];
    const float* a_a2p = (const float*)d_in[24];
    const float* a_a2a = (const float*)d_in[25];

    const int n_p = in_sizes[0] / DIN;
    const int n_a = in_sizes[1] / DIN;
    es.n[0] = n_p; es.n[1] = n_a; es.n[2] = n_p; es.n[3] = n_a;

    float *whb, *ssrcb, *sdstb;
    __nv_bfloat16* whmb;
    int *cntb, *curb, *offb, *partb, *srcpb;
    cudaGetSymbolAddress((void**)&whb,   g_Wh);
    cudaGetSymbolAddress((void**)&whmb,  g_Whm);
    cudaGetSymbolAddress((void**)&ssrcb, g_ssrc);
    cudaGetSymbolAddress((void**)&sdstb, g_sdst);
    cudaGetSymbolAddress((void**)&cntb,  g_cnt);
    cudaGetSymbolAddress((void**)&curb,  g_cur);
    cudaGetSymbolAddress((void**)&offb,  g_off);
    cudaGetSymbolAddress((void**)&partb, g_part);
    cudaGetSymbolAddress((void**)&srcpb, g_srcp);

    float* WhP = whb;                                  // fp32 self P
    float* WhA = whb + (size_t)NP_MAX * DOUT;          // fp32 self A
    __nv_bfloat16* Whm[4];
    for (int i = 0; i < 4; i++) Whm[i] = whmb + (size_t)i * NP_MAX * DOUT;

    float* outP = (float*)d_out;
    float* outA = outP + (size_t)n_p * DOUT;

    // ---- batched CSR build for all 4 edge types ----
    cudaMemsetAsync(cntb, 0, 4 * (size_t)NP_MAX * sizeof(int));
    int Emax = es.E[0];
    for (int t = 1; t < 4; t++) if (es.E[t] > Emax) Emax = es.E[t];
    int nmax = n_p > n_a ? n_p : n_a;
    int NBn = (nmax + 255) / 256;
    hist_all_kernel<<<dim3((Emax + 255) / 256, 4), 256>>>(es, cntb);
    scan1_all_kernel<<<dim3(NBn, 4), 256>>>(es, cntb, partb);
    scan2_all_kernel<<<4, 512>>>(es, partb);
    scan3_all_kernel<<<dim3(NBn, 4), 256>>>(es, cntb, partb, offb, curb);
    fill_all_kernel<<<dim3((Emax + 255) / 256, 4), 256>>>(es, curb, srcpb);

    // ---- tensor-core GEMMs: one launch per node type, 3 weight groups each ----
    cudaFuncSetAttribute(gemm_tc_kernel, cudaFuncAttributeMaxDynamicSharedMemorySize, SMEM_DYN);

    GemmArgs gp;
    gp.A = feat_P; gp.M = n_p;
    gp.W[0] = W_P;   gp.bias[0] = b_P;   gp.C[0] = WhP;     gp.Cb[0] = nullptr;
    gp.W[1] = W_p2p; gp.bias[1] = b_p2p; gp.C[1] = nullptr; gp.Cb[1] = Whm[0];
    gp.W[2] = W_p2a; gp.bias[2] = b_p2a; gp.C[2] = nullptr; gp.Cb[2] = Whm[1];
    gp.av0[0] = a_p2p + DOUT; gp.s0[0] = sdstb + 0 * NP_MAX;
    gp.av1[0] = a_a2p + DOUT; gp.s1[0] = sdstb + 2 * NP_MAX;
    gp.av0[1] = a_p2p;        gp.s0[1] = ssrcb + 0 * NP_MAX;
    gp.av1[1] = nullptr;      gp.s1[1] = nullptr;
    gp.av0[2] = a_p2a;        gp.s0[2] = ssrcb + 1 * NP_MAX;
    gp.av1[2] = nullptr;      gp.s1[2] = nullptr;

    GemmArgs gaa;
    gaa.A = feat_A; gaa.M = n_a;
    gaa.W[0] = W_A;   gaa.bias[0] = b_A;   gaa.C[0] = WhA;     gaa.Cb[0] = nullptr;
    gaa.W[1] = W_a2p; gaa.bias[1] = b_a2p; gaa.C[1] = nullptr; gaa.Cb[1] = Whm[2];
    gaa.W[2] = W_a2a; gaa.bias[2] = b_a2a; gaa.C[2] = nullptr; gaa.Cb[2] = Whm[3];
    gaa.av0[0] = a_p2a + DOUT; gaa.s0[0] = sdstb + 1 * NP_MAX;
    gaa.av1[0] = a_a2a + DOUT; gaa.s1[0] = sdstb + 3 * NP_MAX;
    gaa.av0[1] = a_a2p;        gaa.s0[1] = ssrcb + 2 * NP_MAX;
    gaa.av1[1] = nullptr;      gaa.s1[1] = nullptr;
    gaa.av0[2] = a_a2a;        gaa.s0[2] = ssrcb + 3 * NP_MAX;
    gaa.av1[2] = nullptr;      gaa.s1[2] = nullptr;

    gemm_tc_kernel<<<dim3(3, (n_p + 127) / 128), 256, SMEM_DYN>>>(gp);
    gemm_tc_kernel<<<dim3(3, (n_a + 127) / 128), 256, SMEM_DYN>>>(gaa);

    // ---- fused aggregate + ReLU (one warp per dst node) ----
    // P receives p2p (t0) and a2p (t2); A receives p2a (t1) and a2a (t3).
    gat_aggregate_kernel<<<(n_p + 7) / 8, 256>>>(
        offb + 0 * (NP_MAX + 1), srcpb + (size_t)0 * E_MAX, ssrcb + 0 * NP_MAX, sdstb + 0 * NP_MAX, Whm[0],
        offb + 2 * (NP_MAX + 1), srcpb + (size_t)2 * E_MAX, ssrcb + 2 * NP_MAX, sdstb + 2 * NP_MAX, Whm[2],
        WhP, outP, n_p);
    gat_aggregate_kernel<<<(n_a + 7) / 8, 256>>>(
        offb + 1 * (NP_MAX + 1), srcpb + (size_t)1 * E_MAX, ssrcb + 1 * NP_MAX, sdstb + 1 * NP_MAX, Whm[1],
        offb + 3 * (NP_MAX + 1), srcpb + (size_t)3 * E_MAX, ssrcb + 3 * NP_MAX, sdstb + 3 * NP_MAX, Whm[3],
        WhA, outA, n_a);
}